// round 3
// baseline (speedup 1.0000x reference)
#include <cuda_runtime.h>
#include <cstdint>

#define S 256
#define E 64
#define KNB 20
#define NTHREADS 256
#define NWARPS 8
#define QCTAS 4    // CTAs per batch (each owns 32 of the 128 constant-work row pairs)

// shared memory layout (in floats)
#define XS_OFF   0        // 16384: Xs[e][j], e-major stride 256
#define SROW_OFF 16384    // 8192: per-warp 4 normalized-sims row buffers
#define TW_OFF   24576    // 256
#define IW_OFF   24832    // 256
#define RED_OFF  25088    // 64 (8B aligned) reduction scratch
#define WT_OFF   25152    // 96: a1,a2,a3,b1,w2,b2
#define SMEM_FLOATS 25248
#define SMEM_BYTES (SMEM_FLOATS * 4)

typedef unsigned long long ull;

// per-CTA partial top-20 candidate keys (0 = invalid)
__device__ ull g_cand[S * QCTAS * KNB];

// ---- packed fp32 helpers (Blackwell f32x2 datapath; PTX-only) ----
__device__ __forceinline__ ull pack2(float lo, float hi) {
    ull r; asm("mov.b64 %0, {%1, %2};" : "=l"(r) : "f"(lo), "f"(hi)); return r;
}
__device__ __forceinline__ void unpack2(ull v, float& lo, float& hi) {
    asm("mov.b64 {%0, %1}, %2;" : "=f"(lo), "=f"(hi) : "l"(v));
}
__device__ __forceinline__ ull ffma2(ull a, ull b, ull c) {
    ull d; asm("fma.rn.f32x2 %0, %1, %2, %3;" : "=l"(d) : "l"(a), "l"(b), "l"(c)); return d;
}
__device__ __forceinline__ ull fmul2(ull a, ull b) {
    ull d; asm("mul.rn.f32x2 %0, %1, %2;" : "=l"(d) : "l"(a), "l"(b)); return d;
}

__global__ __launch_bounds__(NTHREADS, 2)
void ugc_kernel(const float* __restrict__ item,
                const float* __restrict__ tsg,
                const float* __restrict__ iwg,
                const float* __restrict__ gW1,
                const float* __restrict__ gb1,
                const float* __restrict__ gW2,
                const float* __restrict__ gb2)
{
    extern __shared__ float sm[];
    float* Xs    = sm + XS_OFF;
    float* srow  = sm + SROW_OFF;
    float* s_tw  = sm + TW_OFF;
    float* s_iw  = sm + IW_OFF;
    float* s_red = sm + RED_OFF;
    float* s_wt  = sm + WT_OFF;

    const int cta = blockIdx.x;          // 0..1023
    const int b   = cta >> 2;            // batch
    const int q   = cta & 3;             // quarter
    const int tid = threadIdx.x;
    const int w   = tid >> 5;
    const int l   = tid & 31;

    // ---- stage MLP weights into smem (tiny) ----
    if (tid < 16) {
        s_wt[tid]      = gW1[tid];        // a1
        s_wt[16 + tid] = gW1[16 + tid];   // a2
        s_wt[32 + tid] = gW1[32 + tid];   // a3
        s_wt[48 + tid] = gb1[tid];        // b1
        s_wt[64 + tid] = gW2[tid];        // w2
    }
    if (tid == 0) s_wt[80] = gb2[0];

    // ---- timestamps max -> temporal weights; interaction weights ----
    const float tsv = tsg[b * S + tid];
    float v = tsv;
    #pragma unroll
    for (int o = 16; o > 0; o >>= 1) v = fmaxf(v, __shfl_xor_sync(0xffffffffu, v, o));
    if (l == 0) s_red[w] = v;
    __syncthreads();
    float tmax = s_red[0];
    #pragma unroll
    for (int r = 1; r < NWARPS; r++) tmax = fmaxf(tmax, s_red[r]);
    const float LN095 = -0.05129329438755058f;      // ln(0.95)
    s_tw[tid] = __expf(LN095 * (tmax - tsv));       // 0.95^(tmax - ts)
    s_iw[tid] = iwg[b * S + tid];

    // ---- stage X transposed into SMEM: Xs[e*256 + j] = X[j][e] ----
    const float* Xg = item + (size_t)b * (S * E);
    #pragma unroll 4
    for (int idx = tid; idx < S * E; idx += NTHREADS) {
        int e = idx >> 8;
        int j = idx & 255;
        Xs[idx] = Xg[j * E + e];
    }
    __syncthreads();

    // ---- per-thread top-K (sorted ascending register list of packed keys) ----
    ull best[KNB];
    #pragma unroll
    for (int n = 0; n < KNB; n++) best[n] = 0ull;
    ull bmin = 0ull;

    // ---- 2 passes; warp owns pairs (m0,255-m0),(m0+1,254-m0) -> rows {m0,m0+1,254-m0,255-m0}
    for (int pass = 0; pass < 2; pass++) {
        const int m0 = q * 32 + pass * 16 + 2 * w;
        const int r0 = m0;
        const int r1 = m0 + 1;
        const int r2 = 254 - m0;
        const int r3 = 255 - m0;

        // 4x256 gram block, packed-pair accumulators: acc[row][p] covers j pairs
        ull A00=0,A01=0,A02=0,A03=0;   // row r0: j = {4l,4l+1},{4l+2,4l+3},{128+4l,..},{128+4l+2,..}
        ull A10=0,A11=0,A12=0,A13=0;
        ull A20=0,A21=0,A22=0,A23=0;
        ull A30=0,A31=0,A32=0,A33=0;

        const float* bp = Xs;
        #pragma unroll 8
        for (int e = 0; e < E; e++) {
            ulonglong2 Av = *(const ulonglong2*)(bp + 4 * l);        // 4 floats = 2 pairs
            ulonglong2 Bv = *(const ulonglong2*)(bp + 128 + 4 * l);
            ull x0 = pack2(bp[r0], bp[r0]);
            ull x1 = pack2(bp[r1], bp[r1]);
            ull x2 = pack2(bp[r2], bp[r2]);
            ull x3 = pack2(bp[r3], bp[r3]);
            A00 = ffma2(x0, Av.x, A00); A01 = ffma2(x0, Av.y, A01);
            A02 = ffma2(x0, Bv.x, A02); A03 = ffma2(x0, Bv.y, A03);
            A10 = ffma2(x1, Av.x, A10); A11 = ffma2(x1, Av.y, A11);
            A12 = ffma2(x1, Bv.x, A12); A13 = ffma2(x1, Bv.y, A13);
            A20 = ffma2(x2, Av.x, A20); A21 = ffma2(x2, Av.y, A21);
            A22 = ffma2(x2, Bv.x, A22); A23 = ffma2(x2, Bv.y, A23);
            A30 = ffma2(x3, Av.x, A30); A31 = ffma2(x3, Av.y, A31);
            A32 = ffma2(x3, Bv.x, A32); A33 = ffma2(x3, Bv.y, A33);
            bp += S;
        }

        // row norms (over ALL 256 cols) + normalized store to srow (packed)
        #define DO_NORM(P0,P1,P2,P3,Q)                                                   \
        {                                                                                \
            ull nsq2 = 0ull;                                                             \
            nsq2 = ffma2(P0,P0,nsq2); nsq2 = ffma2(P1,P1,nsq2);                          \
            nsq2 = ffma2(P2,P2,nsq2); nsq2 = ffma2(P3,P3,nsq2);                          \
            float nlo, nhi; unpack2(nsq2, nlo, nhi);                                     \
            float nsq = nlo + nhi;                                                       \
            _Pragma("unroll")                                                            \
            for (int o = 16; o > 0; o >>= 1) nsq += __shfl_xor_sync(0xffffffffu,nsq,o);  \
            float inv = 1.0f / fmaxf(sqrtf(nsq), 1e-12f);                                \
            ull inv2 = pack2(inv, inv);                                                  \
            float* rb_ = srow + ((w << 2) + (Q)) * S;                                    \
            *(ulonglong2*)(rb_ + 4*l)       = make_ulonglong2(fmul2(P0,inv2), fmul2(P1,inv2)); \
            *(ulonglong2*)(rb_ + 128 + 4*l) = make_ulonglong2(fmul2(P2,inv2), fmul2(P3,inv2)); \
        }
        DO_NORM(A00,A01,A02,A03,0)
        DO_NORM(A10,A11,A12,A13,1)
        DO_NORM(A20,A21,A22,A23,2)
        DO_NORM(A30,A31,A32,A33,3)
        #undef DO_NORM
        __syncwarp();

        // ---- MLP + threshold + top-k over this warp's 4 rows ----
        float c1[16], c2[16], cw2[16];
        #pragma unroll
        for (int k = 0; k < 16; k++) {
            c1[k]  = s_wt[k];
            c2[k]  = s_wt[16 + k];
            cw2[k] = s_wt[64 + k];
        }
        const float b2v = s_wt[80];

        #pragma unroll
        for (int qq = 0; qq < 4; qq++) {
            const int i = (qq == 0) ? r0 : (qq == 1) ? r1 : (qq == 2) ? r2 : r3;
            const float* rb = srow + ((w << 2) + qq) * S;
            const float twi = s_tw[i];
            const float wvi = s_iw[i];
            float rbase[16];
            #pragma unroll
            for (int k = 0; k < 16; k++)
                rbase[k] = fmaf(s_wt[32 + k], wvi, s_wt[48 + k]);   // a3*iw + b1

            const int flatbase = i << 8;
            for (int j = i + 1 + l; j < S; j += 32) {
                float s = rb[j];
                float t = twi * s_tw[j];
                float acc = b2v;
                #pragma unroll
                for (int k = 0; k < 16; k++) {
                    float pre = fmaf(c1[k], s, fmaf(c2[k], t, rbase[k]));
                    acc = fmaf(fmaxf(pre, 0.0f), cw2[k], acc);
                }
                float val = __fdividef(1.0f, 1.0f + __expf(-acc));   // sigmoid
                if (val > 0.1f) {
                    ull key = ((ull)__float_as_uint(val) << 32)
                            | (ull)(0xffffffffu - (unsigned)(flatbase + j));
                    if (key > bmin) {
                        best[0] = key;
                        #pragma unroll
                        for (int n = 0; n < KNB - 1; n++) {
                            ull x = best[n], y = best[n + 1];
                            ull lo = (x < y) ? x : y;
                            ull hi = (x < y) ? y : x;
                            best[n] = lo; best[n + 1] = hi;
                        }
                        bmin = best[0];
                    }
                }
            }
        }
        __syncwarp();
    }

    // ---- merge 256 per-thread lists -> this CTA's top-20 -> global scratch ----
    __syncthreads();
    ull* wred = (ull*)s_red;
    for (int r = 0; r < KNB; r++) {
        ull m = 0ull;
        #pragma unroll
        for (int n = 0; n < KNB; n++) m = (best[n] > m) ? best[n] : m;
        #pragma unroll
        for (int o = 16; o > 0; o >>= 1) {
            ull other = __shfl_xor_sync(0xffffffffu, m, o);
            m = (other > m) ? other : m;
        }
        if (l == 0) wred[w] = m;
        __syncthreads();
        ull g = wred[0];
        #pragma unroll
        for (int q2 = 1; q2 < NWARPS; q2++) { ull o2 = wred[q2]; g = (o2 > g) ? o2 : g; }

        if (g != 0ull) {
            #pragma unroll
            for (int n = 0; n < KNB; n++) if (best[n] == g) best[n] = 0ull;  // unique owner
        }
        if (tid == 0) g_cand[cta * KNB + r] = g;
        __syncthreads();
    }
}

// merge 4 partial top-20 lists per batch -> final top-20 + outputs
__global__ __launch_bounds__(32)
void merge_kernel(float* __restrict__ out)
{
    const int b = blockIdx.x;
    const int l = threadIdx.x;
    const ull* cb = g_cand + b * (QCTAS * KNB);    // 80 candidates

    ull c0 = cb[l];
    ull c1 = cb[32 + l];
    ull c2 = (l < 16) ? cb[64 + l] : 0ull;

    float* oSrc = out;
    float* oDst = out + S * KNB;
    float* oW   = out + 2 * S * KNB;

    for (int r = 0; r < KNB; r++) {
        ull m = c0;
        m = (c1 > m) ? c1 : m;
        m = (c2 > m) ? c2 : m;
        #pragma unroll
        for (int o = 16; o > 0; o >>= 1) {
            ull other = __shfl_xor_sync(0xffffffffu, m, o);
            m = (other > m) ? other : m;
        }
        if (m != 0ull) {           // keys are unique (index embedded)
            if (c0 == m) c0 = 0ull;
            if (c1 == m) c1 = 0ull;
            if (c2 == m) c2 = 0ull;
        }
        if (l == 0) {
            int slot = b * KNB + r;
            if (m != 0ull) {
                float    val  = __uint_as_float((unsigned)(m >> 32));
                unsigned flat = 0xffffffffu - (unsigned)(m & 0xffffffffu);
                int ii = flat >> 8, jj = flat & 255;
                oSrc[slot] = (float)(b * S + ii);
                oDst[slot] = (float)(b * S + jj);
                oW[slot]   = val;
            } else {
                oSrc[slot] = 0.0f; oDst[slot] = 0.0f; oW[slot] = 0.0f;
            }
        }
        __syncwarp();
    }
}

extern "C" void kernel_launch(void* const* d_in, const int* in_sizes, int n_in,
                              void* d_out, int out_size)
{
    // metadata order: user_embeddings(unused), item_embeddings, timestamps,
    // interaction_weights, W1, b1, W2, b2, k_neighbors(=20, hardcoded)
    const float* item = (const float*)d_in[1];
    const float* tsg  = (const float*)d_in[2];
    const float* iwg  = (const float*)d_in[3];
    const float* W1   = (const float*)d_in[4];
    const float* b1   = (const float*)d_in[5];
    const float* W2   = (const float*)d_in[6];
    const float* b2   = (const float*)d_in[7];
    float* out = (float*)d_out;

    cudaFuncSetAttribute(ugc_kernel, cudaFuncAttributeMaxDynamicSharedMemorySize, SMEM_BYTES);
    ugc_kernel<<<S * QCTAS, NTHREADS, SMEM_BYTES>>>(item, tsg, iwg, W1, b1, W2, b2);
    merge_kernel<<<S, 32>>>(out);
}

// round 4
// speedup vs baseline: 1.0215x; 1.0215x over previous
#include <cuda_runtime.h>
#include <cstdint>

#define S 256
#define E 64
#define KNB 20
#define NTHREADS 256
#define NWARPS 8
#define QCTAS 4    // CTAs per batch (each owns 32 of the 128 constant-work row pairs)

// logit(0.1): sigmoid(acc) > 0.1  <=>  acc > LOGIT_THR
#define LOGIT_THR (-2.1972245773362196f)

// shared memory layout (in floats)
#define XS_OFF   0        // 16384: Xs[e][j], e-major stride 256
#define SROW_OFF 16384    // 8192: per-warp 4 normalized-sims row buffers
#define TW_OFF   24576    // 256
#define IW_OFF   24832    // 256
#define RED_OFF  25088    // 64 (8B aligned) reduction scratch
#define WT_OFF   25152    // 96: a1,a2,a3,b1,w2,b2
#define SMEM_FLOATS 25248
#define SMEM_BYTES (SMEM_FLOATS * 4)

typedef unsigned long long ull;

// per-CTA partial top-20 candidate keys (0 = invalid)
__device__ ull g_cand[S * QCTAS * KNB];

// order-preserving uint32 of a float (handles negatives)
__device__ __forceinline__ unsigned f2ord(float f) {
    unsigned u = __float_as_uint(f);
    return u ^ ((u & 0x80000000u) ? 0xffffffffu : 0x80000000u);
}

__global__ __launch_bounds__(NTHREADS, 2)
void ugc_kernel(const float* __restrict__ item,
                const float* __restrict__ tsg,
                const float* __restrict__ iwg,
                const float* __restrict__ gW1,
                const float* __restrict__ gb1,
                const float* __restrict__ gW2,
                const float* __restrict__ gb2)
{
    extern __shared__ float sm[];
    float* Xs    = sm + XS_OFF;
    float* srow  = sm + SROW_OFF;
    float* s_tw  = sm + TW_OFF;
    float* s_iw  = sm + IW_OFF;
    float* s_red = sm + RED_OFF;
    float* s_wt  = sm + WT_OFF;

    const int cta = blockIdx.x;          // 0..1023
    const int b   = cta >> 2;            // batch
    const int q   = cta & 3;             // quarter
    const int tid = threadIdx.x;
    const int w   = tid >> 5;
    const int l   = tid & 31;

    // ---- stage MLP weights into smem (tiny) ----
    if (tid < 16) {
        s_wt[tid]      = gW1[tid];        // a1
        s_wt[16 + tid] = gW1[16 + tid];   // a2
        s_wt[32 + tid] = gW1[32 + tid];   // a3
        s_wt[48 + tid] = gb1[tid];        // b1
        s_wt[64 + tid] = gW2[tid];        // w2
    }
    if (tid == 0) s_wt[80] = gb2[0];

    // ---- timestamps max -> temporal weights; interaction weights ----
    const float tsv = tsg[b * S + tid];
    float v = tsv;
    #pragma unroll
    for (int o = 16; o > 0; o >>= 1) v = fmaxf(v, __shfl_xor_sync(0xffffffffu, v, o));
    if (l == 0) s_red[w] = v;
    __syncthreads();
    float tmax = s_red[0];
    #pragma unroll
    for (int r = 1; r < NWARPS; r++) tmax = fmaxf(tmax, s_red[r]);
    const float LN095 = -0.05129329438755058f;      // ln(0.95)
    s_tw[tid] = __expf(LN095 * (tmax - tsv));       // 0.95^(tmax - ts)
    s_iw[tid] = iwg[b * S + tid];

    // ---- stage X transposed into SMEM: Xs[e*256 + j] = X[j][e] ----
    const float* Xg = item + (size_t)b * (S * E);
    #pragma unroll 4
    for (int idx = tid; idx < S * E; idx += NTHREADS) {
        int e = idx >> 8;
        int j = idx & 255;
        Xs[idx] = Xg[j * E + e];
    }
    __syncthreads();

    // ---- per-thread top-K (sorted ascending register list of packed keys) ----
    ull best[KNB];
    #pragma unroll
    for (int n = 0; n < KNB; n++) best[n] = 0ull;
    ull bmin = 0ull;

    // ---- 2 passes; warp owns rows {m0, m0+1, 254-m0, 255-m0} (510 triu points, constant) ----
    for (int pass = 0; pass < 2; pass++) {
        const int m0 = q * 32 + pass * 16 + 2 * w;
        const int r0 = m0;
        const int r1 = m0 + 1;
        const int r2 = 254 - m0;
        const int r3 = 255 - m0;

        // 4x256 gram block: 32 accumulators, j-loads amortized over 4 rows
        float a00=0,a01=0,a02=0,a03=0,a04=0,a05=0,a06=0,a07=0;
        float a10=0,a11=0,a12=0,a13=0,a14=0,a15=0,a16=0,a17=0;
        float a20=0,a21=0,a22=0,a23=0,a24=0,a25=0,a26=0,a27=0;
        float a30=0,a31=0,a32=0,a33=0,a34=0,a35=0,a36=0,a37=0;

        const float* bp = Xs;
        #pragma unroll 8
        for (int e = 0; e < E; e++) {
            float4 A  = *(const float4*)(bp + 4 * l);
            float4 Bv = *(const float4*)(bp + 128 + 4 * l);
            float x0 = bp[r0], x1 = bp[r1], x2 = bp[r2], x3 = bp[r3];  // broadcasts
            a00=fmaf(x0,A.x,a00); a01=fmaf(x0,A.y,a01); a02=fmaf(x0,A.z,a02); a03=fmaf(x0,A.w,a03);
            a04=fmaf(x0,Bv.x,a04);a05=fmaf(x0,Bv.y,a05);a06=fmaf(x0,Bv.z,a06);a07=fmaf(x0,Bv.w,a07);
            a10=fmaf(x1,A.x,a10); a11=fmaf(x1,A.y,a11); a12=fmaf(x1,A.z,a12); a13=fmaf(x1,A.w,a13);
            a14=fmaf(x1,Bv.x,a14);a15=fmaf(x1,Bv.y,a15);a16=fmaf(x1,Bv.z,a16);a17=fmaf(x1,Bv.w,a17);
            a20=fmaf(x2,A.x,a20); a21=fmaf(x2,A.y,a21); a22=fmaf(x2,A.z,a22); a23=fmaf(x2,A.w,a23);
            a24=fmaf(x2,Bv.x,a24);a25=fmaf(x2,Bv.y,a25);a26=fmaf(x2,Bv.z,a26);a27=fmaf(x2,Bv.w,a27);
            a30=fmaf(x3,A.x,a30); a31=fmaf(x3,A.y,a31); a32=fmaf(x3,A.z,a32); a33=fmaf(x3,A.w,a33);
            a34=fmaf(x3,Bv.x,a34);a35=fmaf(x3,Bv.y,a35);a36=fmaf(x3,Bv.z,a36);a37=fmaf(x3,Bv.w,a37);
            bp += S;
        }

        // row norms (over ALL 256 cols) + normalized store to srow
        #define DO_NORM(A0,A1,A2,A3,A4,A5,A6,A7,Q)                                       \
        {                                                                                \
            float nsq = A0*A0+A1*A1+A2*A2+A3*A3+A4*A4+A5*A5+A6*A6+A7*A7;                 \
            _Pragma("unroll")                                                            \
            for (int o = 16; o > 0; o >>= 1) nsq += __shfl_xor_sync(0xffffffffu,nsq,o);  \
            float inv = 1.0f / fmaxf(sqrtf(nsq), 1e-12f);                                \
            float* rb_ = srow + ((w << 2) + (Q)) * S;                                    \
            *(float4*)(rb_ + 4*l)       = make_float4(A0*inv, A1*inv, A2*inv, A3*inv);   \
            *(float4*)(rb_ + 128 + 4*l) = make_float4(A4*inv, A5*inv, A6*inv, A7*inv);   \
        }
        DO_NORM(a00,a01,a02,a03,a04,a05,a06,a07,0)
        DO_NORM(a10,a11,a12,a13,a14,a15,a16,a17,1)
        DO_NORM(a20,a21,a22,a23,a24,a25,a26,a27,2)
        DO_NORM(a30,a31,a32,a33,a34,a35,a36,a37,3)
        #undef DO_NORM
        __syncwarp();

        // ---- MLP (logit-space) + threshold + top-k over this warp's 4 rows ----
        float c1[16], c2[16], cw2[16];
        #pragma unroll
        for (int k = 0; k < 16; k++) {
            c1[k]  = s_wt[k];
            c2[k]  = s_wt[16 + k];
            cw2[k] = s_wt[64 + k];
        }
        const float b2v = s_wt[80];

        #pragma unroll
        for (int qq = 0; qq < 4; qq++) {
            const int i = (qq == 0) ? r0 : (qq == 1) ? r1 : (qq == 2) ? r2 : r3;
            const float* rb = srow + ((w << 2) + qq) * S;
            const float twi = s_tw[i];
            const float wvi = s_iw[i];
            float rbase[16];
            #pragma unroll
            for (int k = 0; k < 16; k++)
                rbase[k] = fmaf(s_wt[32 + k], wvi, s_wt[48 + k]);   // a3*iw + b1

            const int flatbase = i << 8;

            // one point in logit space; insert into sorted top-k if candidate
            #define DO_POINT(J, ACC)                                                     \
            {                                                                            \
                if ((ACC) > LOGIT_THR) {                                                 \
                    ull key = ((ull)f2ord(ACC) << 32)                                    \
                            | (ull)(0xffffffffu - (unsigned)(flatbase + (J)));           \
                    if (key > bmin) {                                                    \
                        best[0] = key;                                                   \
                        _Pragma("unroll")                                                \
                        for (int n = 0; n < KNB - 1; n++) {                              \
                            ull x = best[n], y = best[n + 1];                            \
                            ull lo = (x < y) ? x : y;                                    \
                            ull hi = (x < y) ? y : x;                                    \
                            best[n] = lo; best[n + 1] = hi;                              \
                        }                                                                \
                        bmin = best[0];                                                  \
                    }                                                                    \
                }                                                                        \
            }

            int j = i + 1 + l;
            // dual independent accumulator chains (j, j+32)
            for (; j + 32 < S; j += 64) {
                float sA = rb[j],      tA = twi * s_tw[j];
                float sB = rb[j + 32], tB = twi * s_tw[j + 32];
                float accA = b2v, accB = b2v;
                #pragma unroll
                for (int k = 0; k < 16; k++) {
                    float preA = fmaf(c1[k], sA, fmaf(c2[k], tA, rbase[k]));
                    float preB = fmaf(c1[k], sB, fmaf(c2[k], tB, rbase[k]));
                    accA = fmaf(fmaxf(preA, 0.0f), cw2[k], accA);
                    accB = fmaf(fmaxf(preB, 0.0f), cw2[k], accB);
                }
                DO_POINT(j, accA)
                DO_POINT(j + 32, accB)
            }
            if (j < S) {
                float sA = rb[j], tA = twi * s_tw[j];
                float accA = b2v;
                #pragma unroll
                for (int k = 0; k < 16; k++) {
                    float preA = fmaf(c1[k], sA, fmaf(c2[k], tA, rbase[k]));
                    accA = fmaf(fmaxf(preA, 0.0f), cw2[k], accA);
                }
                DO_POINT(j, accA)
            }
            #undef DO_POINT
        }
        __syncwarp();
    }

    // ---- merge 256 per-thread lists -> this CTA's top-20 -> global scratch ----
    __syncthreads();
    ull* wred = (ull*)s_red;
    for (int r = 0; r < KNB; r++) {
        ull m = 0ull;
        #pragma unroll
        for (int n = 0; n < KNB; n++) m = (best[n] > m) ? best[n] : m;
        #pragma unroll
        for (int o = 16; o > 0; o >>= 1) {
            ull other = __shfl_xor_sync(0xffffffffu, m, o);
            m = (other > m) ? other : m;
        }
        if (l == 0) wred[w] = m;
        __syncthreads();
        ull g = wred[0];
        #pragma unroll
        for (int q2 = 1; q2 < NWARPS; q2++) { ull o2 = wred[q2]; g = (o2 > g) ? o2 : g; }

        if (g != 0ull) {
            #pragma unroll
            for (int n = 0; n < KNB; n++) if (best[n] == g) best[n] = 0ull;  // unique owner
        }
        if (tid == 0) g_cand[cta * KNB + r] = g;
        __syncthreads();
    }
}

// merge 4 partial top-20 lists per batch -> final top-20, sigmoid, outputs
__global__ __launch_bounds__(32)
void merge_kernel(float* __restrict__ out)
{
    const int b = blockIdx.x;
    const int l = threadIdx.x;
    const ull* cb = g_cand + b * (QCTAS * KNB);    // 80 candidates

    ull c0 = cb[l];
    ull c1 = cb[32 + l];
    ull c2 = (l < 16) ? cb[64 + l] : 0ull;

    float* oSrc = out;
    float* oDst = out + S * KNB;
    float* oW   = out + 2 * S * KNB;

    for (int r = 0; r < KNB; r++) {
        ull m = c0;
        m = (c1 > m) ? c1 : m;
        m = (c2 > m) ? c2 : m;
        #pragma unroll
        for (int o = 16; o > 0; o >>= 1) {
            ull other = __shfl_xor_sync(0xffffffffu, m, o);
            m = (other > m) ? other : m;
        }
        if (m != 0ull) {           // keys are unique (index embedded)
            if (c0 == m) c0 = 0ull;
            if (c1 == m) c1 = 0ull;
            if (c2 == m) c2 = 0ull;
        }
        if (l == 0) {
            int slot = b * KNB + r;
            if (m != 0ull) {
                unsigned u = (unsigned)(m >> 32);
                // inverse of f2ord
                unsigned bits = (u & 0x80000000u) ? (u ^ 0x80000000u) : ~u;
                float acc = __uint_as_float(bits);
                float val = __fdividef(1.0f, 1.0f + __expf(-acc));   // sigmoid
                unsigned flat = 0xffffffffu - (unsigned)(m & 0xffffffffu);
                int ii = flat >> 8, jj = flat & 255;
                oSrc[slot] = (float)(b * S + ii);
                oDst[slot] = (float)(b * S + jj);
                oW[slot]   = val;
            } else {
                oSrc[slot] = 0.0f; oDst[slot] = 0.0f; oW[slot] = 0.0f;
            }
        }
        __syncwarp();
    }
}

extern "C" void kernel_launch(void* const* d_in, const int* in_sizes, int n_in,
                              void* d_out, int out_size)
{
    // metadata order: user_embeddings(unused), item_embeddings, timestamps,
    // interaction_weights, W1, b1, W2, b2, k_neighbors(=20, hardcoded)
    const float* item = (const float*)d_in[1];
    const float* tsg  = (const float*)d_in[2];
    const float* iwg  = (const float*)d_in[3];
    const float* W1   = (const float*)d_in[4];
    const float* b1   = (const float*)d_in[5];
    const float* W2   = (const float*)d_in[6];
    const float* b2   = (const float*)d_in[7];
    float* out = (float*)d_out;

    cudaFuncSetAttribute(ugc_kernel, cudaFuncAttributeMaxDynamicSharedMemorySize, SMEM_BYTES);
    ugc_kernel<<<S * QCTAS, NTHREADS, SMEM_BYTES>>>(item, tsg, iwg, W1, b1, W2, b2);
    merge_kernel<<<S, 32>>>(out);
}

// round 5
// speedup vs baseline: 1.5668x; 1.5338x over previous
#include <cuda_runtime.h>
#include <cstdint>

#define S 256
#define E 64
#define KNB 20
#define NTHREADS 256
#define NWARPS 8
#define XSTRIDE 260   // padded row stride for Xs (16B-aligned, breaks STS conflicts)

// logit(0.1): sigmoid(acc) > 0.1  <=>  acc > LOGIT_THR
#define LOGIT_THR (-2.1972245773362196f)

// shared memory layout (in floats)
#define XS_OFF   0        // 64*260 = 16640: Xs[e][j], e-major stride 260
#define SROW_OFF 16640    // 8192: per-warp 4 normalized-sims row buffers (stride 256)
#define TW_OFF   24832    // 256
#define IW_OFF   25088    // 256
#define RED_OFF  25344    // 64 (8B aligned) reduction scratch
#define WT_OFF   25408    // 96: a1,a2,a3,b1,w2,b2
#define SMEM_FLOATS 25504
#define SMEM_BYTES (SMEM_FLOATS * 4)

typedef unsigned long long ull;

// order-preserving uint32 of a float (handles negatives)
__device__ __forceinline__ unsigned f2ord(float f) {
    unsigned u = __float_as_uint(f);
    return u ^ ((u & 0x80000000u) ? 0xffffffffu : 0x80000000u);
}

__global__ __launch_bounds__(NTHREADS, 2)
void ugc_kernel(const float* __restrict__ item,
                const float* __restrict__ tsg,
                const float* __restrict__ iwg,
                const float* __restrict__ gW1,
                const float* __restrict__ gb1,
                const float* __restrict__ gW2,
                const float* __restrict__ gb2,
                float* __restrict__ out)
{
    extern __shared__ float sm[];
    float* Xs    = sm + XS_OFF;
    float* srow  = sm + SROW_OFF;
    float* s_tw  = sm + TW_OFF;
    float* s_iw  = sm + IW_OFF;
    float* s_red = sm + RED_OFF;
    float* s_wt  = sm + WT_OFF;

    const int b   = blockIdx.x;
    const int tid = threadIdx.x;
    const int w   = tid >> 5;
    const int l   = tid & 31;

    // ---- stage MLP weights into smem (tiny) ----
    if (tid < 16) {
        s_wt[tid]      = gW1[tid];        // a1
        s_wt[16 + tid] = gW1[16 + tid];   // a2
        s_wt[32 + tid] = gW1[32 + tid];   // a3
        s_wt[48 + tid] = gb1[tid];        // b1
        s_wt[64 + tid] = gW2[tid];        // w2
    }
    if (tid == 0) s_wt[80] = gb2[0];

    // ---- timestamps max -> temporal weights; interaction weights ----
    const float tsv = tsg[b * S + tid];
    float v = tsv;
    #pragma unroll
    for (int o = 16; o > 0; o >>= 1) v = fmaxf(v, __shfl_xor_sync(0xffffffffu, v, o));
    if (l == 0) s_red[w] = v;
    __syncthreads();
    float tmax = s_red[0];
    #pragma unroll
    for (int r = 1; r < NWARPS; r++) tmax = fmaxf(tmax, s_red[r]);
    const float LN095 = -0.05129329438755058f;      // ln(0.95)
    s_tw[tid] = __expf(LN095 * (tmax - tsv));       // 0.95^(tmax - ts)
    s_iw[tid] = iwg[b * S + tid];

    // ---- stage X transposed into SMEM via coalesced 4x4 block transpose ----
    // Xs[e*XSTRIDE + j] = X[j][e]
    {
        const float* Xg = item + (size_t)b * (S * E);
        #pragma unroll
        for (int it = 0; it < 4; it++) {
            int blk = it * NTHREADS + tid;      // 0..1023 blocks of 4x4
            int eb  = blk & 15;                 // e-block (16 per row group)
            int jb  = blk >> 4;                 // j-block (64)
            float4 r0 = *(const float4*)(Xg + (4 * jb + 0) * E + 4 * eb);
            float4 r1 = *(const float4*)(Xg + (4 * jb + 1) * E + 4 * eb);
            float4 r2 = *(const float4*)(Xg + (4 * jb + 2) * E + 4 * eb);
            float4 r3 = *(const float4*)(Xg + (4 * jb + 3) * E + 4 * eb);
            *(float4*)(Xs + (4 * eb + 0) * XSTRIDE + 4 * jb) = make_float4(r0.x, r1.x, r2.x, r3.x);
            *(float4*)(Xs + (4 * eb + 1) * XSTRIDE + 4 * jb) = make_float4(r0.y, r1.y, r2.y, r3.y);
            *(float4*)(Xs + (4 * eb + 2) * XSTRIDE + 4 * jb) = make_float4(r0.z, r1.z, r2.z, r3.z);
            *(float4*)(Xs + (4 * eb + 3) * XSTRIDE + 4 * jb) = make_float4(r0.w, r1.w, r2.w, r3.w);
        }
    }
    __syncthreads();

    // ---- per-thread top-K (sorted ascending register list of packed keys) ----
    ull best[KNB];
    #pragma unroll
    for (int n = 0; n < KNB; n++) best[n] = 0ull;
    ull bmin = 0ull;

    // ---- main loop: 8 passes, each warp owns 4 rows {2u, 2u+1, 254-2u, 255-2u} ----
    for (int pass = 0; pass < 8; pass++) {
        const int u  = pass * NWARPS + w;          // 0..63
        const int r0 = 2 * u;
        const int r1 = 2 * u + 1;
        const int r2 = 254 - 2 * u;
        const int r3 = 255 - 2 * u;

        // 4x256 gram block: 32 accumulators, j-loads amortized over 4 rows
        float a00=0,a01=0,a02=0,a03=0,a04=0,a05=0,a06=0,a07=0;
        float a10=0,a11=0,a12=0,a13=0,a14=0,a15=0,a16=0,a17=0;
        float a20=0,a21=0,a22=0,a23=0,a24=0,a25=0,a26=0,a27=0;
        float a30=0,a31=0,a32=0,a33=0,a34=0,a35=0,a36=0,a37=0;

        const float* bp = Xs;
        #pragma unroll 8
        for (int e = 0; e < E; e++) {
            float4 A  = *(const float4*)(bp + 4 * l);
            float4 Bv = *(const float4*)(bp + 128 + 4 * l);
            float x0 = bp[r0], x1 = bp[r1], x2 = bp[r2], x3 = bp[r3];  // broadcasts
            a00=fmaf(x0,A.x,a00); a01=fmaf(x0,A.y,a01); a02=fmaf(x0,A.z,a02); a03=fmaf(x0,A.w,a03);
            a04=fmaf(x0,Bv.x,a04);a05=fmaf(x0,Bv.y,a05);a06=fmaf(x0,Bv.z,a06);a07=fmaf(x0,Bv.w,a07);
            a10=fmaf(x1,A.x,a10); a11=fmaf(x1,A.y,a11); a12=fmaf(x1,A.z,a12); a13=fmaf(x1,A.w,a13);
            a14=fmaf(x1,Bv.x,a14);a15=fmaf(x1,Bv.y,a15);a16=fmaf(x1,Bv.z,a16);a17=fmaf(x1,Bv.w,a17);
            a20=fmaf(x2,A.x,a20); a21=fmaf(x2,A.y,a21); a22=fmaf(x2,A.z,a22); a23=fmaf(x2,A.w,a23);
            a24=fmaf(x2,Bv.x,a24);a25=fmaf(x2,Bv.y,a25);a26=fmaf(x2,Bv.z,a26);a27=fmaf(x2,Bv.w,a27);
            a30=fmaf(x3,A.x,a30); a31=fmaf(x3,A.y,a31); a32=fmaf(x3,A.z,a32); a33=fmaf(x3,A.w,a33);
            a34=fmaf(x3,Bv.x,a34);a35=fmaf(x3,Bv.y,a35);a36=fmaf(x3,Bv.z,a36);a37=fmaf(x3,Bv.w,a37);
            bp += XSTRIDE;
        }

        // row norms (over ALL 256 cols) + normalized store to srow
        #define DO_NORM(A0,A1,A2,A3,A4,A5,A6,A7,Q)                                       \
        {                                                                                \
            float nsq = A0*A0+A1*A1+A2*A2+A3*A3+A4*A4+A5*A5+A6*A6+A7*A7;                 \
            _Pragma("unroll")                                                            \
            for (int o = 16; o > 0; o >>= 1) nsq += __shfl_xor_sync(0xffffffffu,nsq,o);  \
            float inv = 1.0f / fmaxf(sqrtf(nsq), 1e-12f);                                \
            float* rb_ = srow + ((w << 2) + (Q)) * S;                                    \
            *(float4*)(rb_ + 4*l)       = make_float4(A0*inv, A1*inv, A2*inv, A3*inv);   \
            *(float4*)(rb_ + 128 + 4*l) = make_float4(A4*inv, A5*inv, A6*inv, A7*inv);   \
        }
        DO_NORM(a00,a01,a02,a03,a04,a05,a06,a07,0)
        DO_NORM(a10,a11,a12,a13,a14,a15,a16,a17,1)
        DO_NORM(a20,a21,a22,a23,a24,a25,a26,a27,2)
        DO_NORM(a30,a31,a32,a33,a34,a35,a36,a37,3)
        #undef DO_NORM
        __syncwarp();

        // ---- MLP (logit space) + threshold + top-k over this warp's 4 rows ----
        float c1[16], c2[16], cw2[16];
        #pragma unroll
        for (int k = 0; k < 16; k++) {
            c1[k]  = s_wt[k];
            c2[k]  = s_wt[16 + k];
            cw2[k] = s_wt[64 + k];
        }
        const float b2v = s_wt[80];

        #pragma unroll
        for (int qq = 0; qq < 4; qq++) {
            const int i = (qq == 0) ? r0 : (qq == 1) ? r1 : (qq == 2) ? r2 : r3;
            const float* rb = srow + ((w << 2) + qq) * S;
            const float twi = s_tw[i];
            const float wvi = s_iw[i];
            float rbase[16];
            #pragma unroll
            for (int k = 0; k < 16; k++)
                rbase[k] = fmaf(s_wt[32 + k], wvi, s_wt[48 + k]);   // a3*iw + b1

            const int flatbase = i << 8;
            for (int j = i + 1 + l; j < S; j += 32) {
                float s = rb[j];
                float t = twi * s_tw[j];
                float acc = b2v;
                #pragma unroll
                for (int k = 0; k < 16; k++) {
                    float pre = fmaf(c1[k], s, fmaf(c2[k], t, rbase[k]));
                    acc = fmaf(fmaxf(pre, 0.0f), cw2[k], acc);
                }
                if (acc > LOGIT_THR) {    // sigmoid(acc) > 0.1, monotone
                    ull key = ((ull)f2ord(acc) << 32)
                            | (ull)(0xffffffffu - (unsigned)(flatbase + j));
                    if (key > bmin) {
                        best[0] = key;
                        #pragma unroll
                        for (int n = 0; n < KNB - 1; n++) {
                            ull x = best[n], y = best[n + 1];
                            ull lo = (x < y) ? x : y;
                            ull hi = (x < y) ? y : x;
                            best[n] = lo; best[n + 1] = hi;
                        }
                        bmin = best[0];
                    }
                }
            }
        }
        __syncwarp();
    }

    // ---- merge 256 per-thread top-20 lists -> global top-20 (descending) ----
    __syncthreads();
    ull* wred = (ull*)s_red;
    float* oSrc = out;
    float* oDst = out + S * KNB;        // 5120
    float* oW   = out + 2 * S * KNB;    // 10240

    for (int r = 0; r < KNB; r++) {
        ull m = 0ull;
        #pragma unroll
        for (int n = 0; n < KNB; n++) m = (best[n] > m) ? best[n] : m;
        #pragma unroll
        for (int o = 16; o > 0; o >>= 1) {
            ull other = __shfl_xor_sync(0xffffffffu, m, o);
            m = (other > m) ? other : m;
        }
        if (l == 0) wred[w] = m;
        __syncthreads();
        ull g = wred[0];
        #pragma unroll
        for (int q2 = 1; q2 < NWARPS; q2++) { ull o2 = wred[q2]; g = (o2 > g) ? o2 : g; }

        if (g != 0ull) {
            #pragma unroll
            for (int n = 0; n < KNB; n++) if (best[n] == g) best[n] = 0ull;  // unique owner
        }
        if (tid == 0) {
            int slot = b * KNB + r;
            if (g != 0ull) {
                unsigned u = (unsigned)(g >> 32);
                unsigned bits = (u & 0x80000000u) ? (u ^ 0x80000000u) : ~u;  // inverse f2ord
                float acc = __uint_as_float(bits);
                float val = __fdividef(1.0f, 1.0f + __expf(-acc));           // sigmoid (20/batch)
                unsigned flat = 0xffffffffu - (unsigned)(g & 0xffffffffu);
                int ii = flat >> 8, jj = flat & 255;
                oSrc[slot] = (float)(b * S + ii);
                oDst[slot] = (float)(b * S + jj);
                oW[slot]   = val;
            } else {
                oSrc[slot] = 0.0f; oDst[slot] = 0.0f; oW[slot] = 0.0f;
            }
        }
        __syncthreads();
    }
}

extern "C" void kernel_launch(void* const* d_in, const int* in_sizes, int n_in,
                              void* d_out, int out_size)
{
    // metadata order: user_embeddings(unused), item_embeddings, timestamps,
    // interaction_weights, W1, b1, W2, b2, k_neighbors(=20, hardcoded)
    const float* item = (const float*)d_in[1];
    const float* tsg  = (const float*)d_in[2];
    const float* iwg  = (const float*)d_in[3];
    const float* W1   = (const float*)d_in[4];
    const float* b1   = (const float*)d_in[5];
    const float* W2   = (const float*)d_in[6];
    const float* b2   = (const float*)d_in[7];
    float* out = (float*)d_out;

    cudaFuncSetAttribute(ugc_kernel, cudaFuncAttributeMaxDynamicSharedMemorySize, SMEM_BYTES);
    ugc_kernel<<<S, NTHREADS, SMEM_BYTES>>>(item, tsg, iwg, W1, b1, W2, b2, out);
}

// round 6
// speedup vs baseline: 1.6290x; 1.0397x over previous
#include <cuda_runtime.h>
#include <cstdint>

#define S 256
#define E 64
#define KNB 20
#define NTHREADS 256
#define NWARPS 8
#define XSTRIDE 260   // padded row stride for Xs (16B-aligned, breaks STS conflicts)

// logit(0.1): sigmoid(acc) > 0.1  <=>  acc > LOGIT_THR
#define LOGIT_THR (-2.1972245773362196f)

// shared memory layout (in floats)
#define XS_OFF   0        // 64*260 = 16640: Xs[e][j], e-major stride 260 (reused as key dump)
#define SROW_OFF 16640    // 8192: per-warp 4 normalized-sims row buffers (reused as wtop)
#define TW_OFF   24832    // 256
#define IW_OFF   25088    // 256
#define RED_OFF  25344    // 64 (8B aligned) reduction scratch
#define WT_OFF   25408    // 96: a1,a2,a3,b1,w2,b2
#define SMEM_FLOATS 25504
#define SMEM_BYTES (SMEM_FLOATS * 4)

typedef unsigned long long ull;

// order-preserving uint32 of a float (handles negatives)
__device__ __forceinline__ unsigned f2ord(float f) {
    unsigned u = __float_as_uint(f);
    return u ^ ((u & 0x80000000u) ? 0xffffffffu : 0x80000000u);
}

// value (float) encoded in the high word of a key; -big for empty key
__device__ __forceinline__ float keyval(ull g) {
    if (g == 0ull) return -3.0e38f;
    unsigned u = (unsigned)(g >> 32);
    unsigned bits = (u & 0x80000000u) ? (u ^ 0x80000000u) : ~u;   // inverse f2ord
    return __uint_as_float(bits);
}

__device__ __forceinline__ ull wmax64(ull v) {
    #pragma unroll
    for (int o = 16; o > 0; o >>= 1) {
        ull t = __shfl_xor_sync(0xffffffffu, v, o);
        v = (t > v) ? t : v;
    }
    return v;
}

__global__ __launch_bounds__(NTHREADS, 2)
void ugc_kernel(const float* __restrict__ item,
                const float* __restrict__ tsg,
                const float* __restrict__ iwg,
                const float* __restrict__ gW1,
                const float* __restrict__ gb1,
                const float* __restrict__ gW2,
                const float* __restrict__ gb2,
                float* __restrict__ out)
{
    extern __shared__ float sm[];
    float* Xs    = sm + XS_OFF;
    float* srow  = sm + SROW_OFF;
    float* s_tw  = sm + TW_OFF;
    float* s_iw  = sm + IW_OFF;
    float* s_red = sm + RED_OFF;
    float* s_wt  = sm + WT_OFF;

    const int b   = blockIdx.x;
    const int tid = threadIdx.x;
    const int w   = tid >> 5;
    const int l   = tid & 31;

    // ---- stage MLP weights into smem (tiny) ----
    if (tid < 16) {
        s_wt[tid]      = gW1[tid];        // a1
        s_wt[16 + tid] = gW1[16 + tid];   // a2
        s_wt[32 + tid] = gW1[32 + tid];   // a3
        s_wt[48 + tid] = gb1[tid];        // b1
        s_wt[64 + tid] = gW2[tid];        // w2
    }
    if (tid == 0) s_wt[80] = gb2[0];

    // ---- timestamps max -> temporal weights; interaction weights ----
    const float tsv = tsg[b * S + tid];
    float v = tsv;
    #pragma unroll
    for (int o = 16; o > 0; o >>= 1) v = fmaxf(v, __shfl_xor_sync(0xffffffffu, v, o));
    if (l == 0) s_red[w] = v;
    __syncthreads();
    float tmax = s_red[0];
    #pragma unroll
    for (int r = 1; r < NWARPS; r++) tmax = fmaxf(tmax, s_red[r]);
    const float LN095 = -0.05129329438755058f;      // ln(0.95)
    s_tw[tid] = __expf(LN095 * (tmax - tsv));       // 0.95^(tmax - ts)
    s_iw[tid] = iwg[b * S + tid];

    // ---- stage X transposed into SMEM via coalesced 4x4 block transpose ----
    // Xs[e*XSTRIDE + j] = X[j][e]
    {
        const float* Xg = item + (size_t)b * (S * E);
        #pragma unroll
        for (int it = 0; it < 4; it++) {
            int blk = it * NTHREADS + tid;      // 0..1023 blocks of 4x4
            int eb  = blk & 15;                 // e-block (16 per row group)
            int jb  = blk >> 4;                 // j-block (64)
            float4 r0 = *(const float4*)(Xg + (4 * jb + 0) * E + 4 * eb);
            float4 r1 = *(const float4*)(Xg + (4 * jb + 1) * E + 4 * eb);
            float4 r2 = *(const float4*)(Xg + (4 * jb + 2) * E + 4 * eb);
            float4 r3 = *(const float4*)(Xg + (4 * jb + 3) * E + 4 * eb);
            *(float4*)(Xs + (4 * eb + 0) * XSTRIDE + 4 * jb) = make_float4(r0.x, r1.x, r2.x, r3.x);
            *(float4*)(Xs + (4 * eb + 1) * XSTRIDE + 4 * jb) = make_float4(r0.y, r1.y, r2.y, r3.y);
            *(float4*)(Xs + (4 * eb + 2) * XSTRIDE + 4 * jb) = make_float4(r0.z, r1.z, r2.z, r3.z);
            *(float4*)(Xs + (4 * eb + 3) * XSTRIDE + 4 * jb) = make_float4(r0.w, r1.w, r2.w, r3.w);
        }
    }
    __syncthreads();

    // ---- per-thread top-K (sorted ascending register list of packed keys) ----
    ull best[KNB];
    #pragma unroll
    for (int n = 0; n < KNB; n++) best[n] = 0ull;
    ull  warpThr = 0ull;        // warp-wide valid discard bound (some lane holds 20 >= this)
    ull  gate    = 0ull;        // max(warpThr, best[0])
    float gateF  = -3.0e38f;    // float value of gate (fast-path filter)

    // ---- main loop: 8 passes, each warp owns 4 rows {2u, 2u+1, 254-2u, 255-2u} ----
    for (int pass = 0; pass < 8; pass++) {
        const int u  = pass * NWARPS + w;          // 0..63
        const int r0 = 2 * u;
        const int r1 = 2 * u + 1;
        const int r2 = 254 - 2 * u;
        const int r3 = 255 - 2 * u;

        // 4x256 gram block: 32 accumulators, j-loads amortized over 4 rows
        float a00=0,a01=0,a02=0,a03=0,a04=0,a05=0,a06=0,a07=0;
        float a10=0,a11=0,a12=0,a13=0,a14=0,a15=0,a16=0,a17=0;
        float a20=0,a21=0,a22=0,a23=0,a24=0,a25=0,a26=0,a27=0;
        float a30=0,a31=0,a32=0,a33=0,a34=0,a35=0,a36=0,a37=0;

        const float* bp = Xs;
        #pragma unroll 8
        for (int e = 0; e < E; e++) {
            float4 A  = *(const float4*)(bp + 4 * l);
            float4 Bv = *(const float4*)(bp + 128 + 4 * l);
            float x0 = bp[r0], x1 = bp[r1], x2 = bp[r2], x3 = bp[r3];  // broadcasts
            a00=fmaf(x0,A.x,a00); a01=fmaf(x0,A.y,a01); a02=fmaf(x0,A.z,a02); a03=fmaf(x0,A.w,a03);
            a04=fmaf(x0,Bv.x,a04);a05=fmaf(x0,Bv.y,a05);a06=fmaf(x0,Bv.z,a06);a07=fmaf(x0,Bv.w,a07);
            a10=fmaf(x1,A.x,a10); a11=fmaf(x1,A.y,a11); a12=fmaf(x1,A.z,a12); a13=fmaf(x1,A.w,a13);
            a14=fmaf(x1,Bv.x,a14);a15=fmaf(x1,Bv.y,a15);a16=fmaf(x1,Bv.z,a16);a17=fmaf(x1,Bv.w,a17);
            a20=fmaf(x2,A.x,a20); a21=fmaf(x2,A.y,a21); a22=fmaf(x2,A.z,a22); a23=fmaf(x2,A.w,a23);
            a24=fmaf(x2,Bv.x,a24);a25=fmaf(x2,Bv.y,a25);a26=fmaf(x2,Bv.z,a26);a27=fmaf(x2,Bv.w,a27);
            a30=fmaf(x3,A.x,a30); a31=fmaf(x3,A.y,a31); a32=fmaf(x3,A.z,a32); a33=fmaf(x3,A.w,a33);
            a34=fmaf(x3,Bv.x,a34);a35=fmaf(x3,Bv.y,a35);a36=fmaf(x3,Bv.z,a36);a37=fmaf(x3,Bv.w,a37);
            bp += XSTRIDE;
        }

        // row norms (over ALL 256 cols) + normalized store to srow
        #define DO_NORM(A0,A1,A2,A3,A4,A5,A6,A7,Q)                                       \
        {                                                                                \
            float nsq = A0*A0+A1*A1+A2*A2+A3*A3+A4*A4+A5*A5+A6*A6+A7*A7;                 \
            _Pragma("unroll")                                                            \
            for (int o = 16; o > 0; o >>= 1) nsq += __shfl_xor_sync(0xffffffffu,nsq,o);  \
            float inv = 1.0f / fmaxf(sqrtf(nsq), 1e-12f);                                \
            float* rb_ = srow + ((w << 2) + (Q)) * S;                                    \
            *(float4*)(rb_ + 4*l)       = make_float4(A0*inv, A1*inv, A2*inv, A3*inv);   \
            *(float4*)(rb_ + 128 + 4*l) = make_float4(A4*inv, A5*inv, A6*inv, A7*inv);   \
        }
        DO_NORM(a00,a01,a02,a03,a04,a05,a06,a07,0)
        DO_NORM(a10,a11,a12,a13,a14,a15,a16,a17,1)
        DO_NORM(a20,a21,a22,a23,a24,a25,a26,a27,2)
        DO_NORM(a30,a31,a32,a33,a34,a35,a36,a37,3)
        #undef DO_NORM
        __syncwarp();

        // ---- MLP (logit space) + gated top-k over this warp's 4 rows ----
        float c1[16], c2[16], cw2[16];
        #pragma unroll
        for (int k = 0; k < 16; k++) {
            c1[k]  = s_wt[k];
            c2[k]  = s_wt[16 + k];
            cw2[k] = s_wt[64 + k];
        }
        const float b2v = s_wt[80];

        #pragma unroll
        for (int qq = 0; qq < 4; qq++) {
            const int i = (qq == 0) ? r0 : (qq == 1) ? r1 : (qq == 2) ? r2 : r3;
            const float* rb = srow + ((w << 2) + qq) * S;
            const float twi = s_tw[i];
            const float wvi = s_iw[i];
            float rbase[16];
            #pragma unroll
            for (int k = 0; k < 16; k++)
                rbase[k] = fmaf(s_wt[32 + k], wvi, s_wt[48 + k]);   // a3*iw + b1

            // refresh warp-wide threshold (valid: max over lanes of full-list minima;
            // empty-list lanes contribute best[0]==0 which is neutral)
            __syncwarp();
            {
                ull t2 = wmax64(best[0]);
                warpThr = (t2 > warpThr) ? t2 : warpThr;
                gate = (warpThr > best[0]) ? warpThr : best[0];
                gateF = keyval(gate);
            }

            const int flatbase = i << 8;
            for (int j = i + 1 + l; j < S; j += 32) {
                float s = rb[j];
                float t = twi * s_tw[j];
                float acc = b2v;
                #pragma unroll
                for (int k = 0; k < 16; k++) {
                    float pre = fmaf(c1[k], s, fmaf(c2[k], t, rbase[k]));
                    acc = fmaf(fmaxf(pre, 0.0f), cw2[k], acc);
                }
                // fast float gate; exact 64-bit tie-break only for real candidates
                if (acc > LOGIT_THR && acc >= gateF) {
                    ull key = ((ull)f2ord(acc) << 32)
                            | (ull)(0xffffffffu - (unsigned)(flatbase + j));
                    if (key > gate) {
                        best[0] = key;
                        #pragma unroll
                        for (int n = 0; n < KNB - 1; n++) {
                            ull x = best[n], y = best[n + 1];
                            ull lo = (x < y) ? x : y;
                            ull hi = (x < y) ? y : x;
                            best[n] = lo; best[n + 1] = hi;
                        }
                        gate = (warpThr > best[0]) ? warpThr : best[0];
                        gateF = keyval(gate);
                    }
                }
            }
        }
        __syncwarp();
    }

    // ---- hierarchical merge: dump sorted lists -> warp top-20 -> CTA top-20 ----
    __syncthreads();                       // all warps done with Xs/srow
    ull* dump = (ull*)sm;                  // 256*20 ull = 40KB (inside Xs region)
    #pragma unroll
    for (int n = 0; n < KNB; n++) dump[tid * KNB + n] = best[n];
    __syncthreads();

    ull* wtop = (ull*)(sm + SROW_OFF);     // 8*20 ull
    {
        const ull* ml = dump + tid * KNB;  // own sorted-ascending list
        int p = KNB - 1;
        ull cand = ml[p];
        for (int r = 0; r < KNB; r++) {
            ull m = wmax64(cand);
            if (cand == m && m != 0ull) { p--; cand = (p >= 0) ? ml[p] : 0ull; }
            if (l == 0) wtop[w * KNB + r] = m;     // descending
        }
    }
    __syncthreads();

    if (w == 0) {
        float* oSrc = out;
        float* oDst = out + S * KNB;        // 5120
        float* oW   = out + 2 * S * KNB;    // 10240
        int p = 0;
        ull cand = (l < NWARPS) ? wtop[l * KNB] : 0ull;
        for (int r = 0; r < KNB; r++) {
            ull m = wmax64(cand);
            if (l < NWARPS && cand == m && m != 0ull) {
                p++;
                cand = (p < KNB) ? wtop[l * KNB + p] : 0ull;
            }
            if (l == 0) {
                int slot = b * KNB + r;
                if (m != 0ull) {
                    float acc = keyval(m);
                    float val = __fdividef(1.0f, 1.0f + __expf(-acc));   // sigmoid (20/batch)
                    unsigned flat = 0xffffffffu - (unsigned)(m & 0xffffffffu);
                    int ii = flat >> 8, jj = flat & 255;
                    oSrc[slot] = (float)(b * S + ii);
                    oDst[slot] = (float)(b * S + jj);
                    oW[slot]   = val;
                } else {
                    oSrc[slot] = 0.0f; oDst[slot] = 0.0f; oW[slot] = 0.0f;
                }
            }
        }
    }
}

extern "C" void kernel_launch(void* const* d_in, const int* in_sizes, int n_in,
                              void* d_out, int out_size)
{
    // metadata order: user_embeddings(unused), item_embeddings, timestamps,
    // interaction_weights, W1, b1, W2, b2, k_neighbors(=20, hardcoded)
    const float* item = (const float*)d_in[1];
    const float* tsg  = (const float*)d_in[2];
    const float* iwg  = (const float*)d_in[3];
    const float* W1   = (const float*)d_in[4];
    const float* b1   = (const float*)d_in[5];
    const float* W2   = (const float*)d_in[6];
    const float* b2   = (const float*)d_in[7];
    float* out = (float*)d_out;

    cudaFuncSetAttribute(ugc_kernel, cudaFuncAttributeMaxDynamicSharedMemorySize, SMEM_BYTES);
    ugc_kernel<<<S, NTHREADS, SMEM_BYTES>>>(item, tsg, iwg, W1, b1, W2, b2, out);
}

// round 7
// speedup vs baseline: 1.6310x; 1.0013x over previous
#include <cuda_runtime.h>
#include <cstdint>

#define S 256
#define E 64
#define KNB 20
#define NTHREADS 256
#define NWARPS 8
#define XSTRIDE 260   // padded row stride for Xs (16B-aligned, breaks STS conflicts)

// logit(0.1): sigmoid(acc) > 0.1  <=>  acc > LOGIT_THR
#define LOGIT_THR (-2.1972245773362196f)

// shared memory layout (in floats)
#define XS_OFF   0        // 64*260 = 16640: Xs[e][j], e-major stride 260 (reused as key dump)
#define SROW_OFF 16640    // 8192: per-warp 4 normalized-sims row buffers (reused as wtop)
#define TW_OFF   24832    // 256
#define IW_OFF   25088    // 256
#define RED_OFF  25344    // 64 (8B aligned) reduction scratch
#define WT_OFF   25408    // 96: a1,a2,a3,b1,w2,b2
#define SMEM_FLOATS 25504
#define SMEM_BYTES (SMEM_FLOATS * 4)

typedef unsigned long long ull;

// order-preserving uint32 of a float (handles negatives)
__device__ __forceinline__ unsigned f2ord(float f) {
    unsigned u = __float_as_uint(f);
    return u ^ ((u & 0x80000000u) ? 0xffffffffu : 0x80000000u);
}

// value (float) encoded in the high word of a key; -big for empty key
__device__ __forceinline__ float keyval(ull g) {
    if (g == 0ull) return -3.0e38f;
    unsigned u = (unsigned)(g >> 32);
    unsigned bits = (u & 0x80000000u) ? (u ^ 0x80000000u) : ~u;   // inverse f2ord
    return __uint_as_float(bits);
}

__device__ __forceinline__ ull wmax64(ull v) {
    #pragma unroll
    for (int o = 16; o > 0; o >>= 1) {
        ull t = __shfl_xor_sync(0xffffffffu, v, o);
        v = (t > v) ? t : v;
    }
    return v;
}

__global__ __launch_bounds__(NTHREADS, 2)
void ugc_kernel(const float* __restrict__ item,
                const float* __restrict__ tsg,
                const float* __restrict__ iwg,
                const float* __restrict__ gW1,
                const float* __restrict__ gb1,
                const float* __restrict__ gW2,
                const float* __restrict__ gb2,
                float* __restrict__ out)
{
    extern __shared__ float sm[];
    float* Xs    = sm + XS_OFF;
    float* srow  = sm + SROW_OFF;
    float* s_tw  = sm + TW_OFF;
    float* s_iw  = sm + IW_OFF;
    float* s_red = sm + RED_OFF;
    float* s_wt  = sm + WT_OFF;

    const int b   = blockIdx.x;
    const int tid = threadIdx.x;
    const int w   = tid >> 5;
    const int l   = tid & 31;

    // ---- stage MLP weights into smem (tiny) ----
    if (tid < 16) {
        s_wt[tid]      = gW1[tid];        // a1
        s_wt[16 + tid] = gW1[16 + tid];   // a2
        s_wt[32 + tid] = gW1[32 + tid];   // a3
        s_wt[48 + tid] = gb1[tid];        // b1
        s_wt[64 + tid] = gW2[tid];        // w2
    }
    if (tid == 0) s_wt[80] = gb2[0];

    // ---- timestamps max -> temporal weights; interaction weights ----
    const float tsv = tsg[b * S + tid];
    float v = tsv;
    #pragma unroll
    for (int o = 16; o > 0; o >>= 1) v = fmaxf(v, __shfl_xor_sync(0xffffffffu, v, o));
    if (l == 0) s_red[w] = v;
    __syncthreads();
    float tmax = s_red[0];
    #pragma unroll
    for (int r = 1; r < NWARPS; r++) tmax = fmaxf(tmax, s_red[r]);
    const float LN095 = -0.05129329438755058f;      // ln(0.95)
    s_tw[tid] = __expf(LN095 * (tmax - tsv));       // 0.95^(tmax - ts)
    s_iw[tid] = iwg[b * S + tid];

    // ---- stage X transposed into SMEM via coalesced 4x4 block transpose ----
    // Xs[e*XSTRIDE + j] = X[j][e]
    {
        const float* Xg = item + (size_t)b * (S * E);
        #pragma unroll
        for (int it = 0; it < 4; it++) {
            int blk = it * NTHREADS + tid;      // 0..1023 blocks of 4x4
            int eb  = blk & 15;                 // e-block (16 per row group)
            int jb  = blk >> 4;                 // j-block (64)
            float4 r0 = *(const float4*)(Xg + (4 * jb + 0) * E + 4 * eb);
            float4 r1 = *(const float4*)(Xg + (4 * jb + 1) * E + 4 * eb);
            float4 r2 = *(const float4*)(Xg + (4 * jb + 2) * E + 4 * eb);
            float4 r3 = *(const float4*)(Xg + (4 * jb + 3) * E + 4 * eb);
            *(float4*)(Xs + (4 * eb + 0) * XSTRIDE + 4 * jb) = make_float4(r0.x, r1.x, r2.x, r3.x);
            *(float4*)(Xs + (4 * eb + 1) * XSTRIDE + 4 * jb) = make_float4(r0.y, r1.y, r2.y, r3.y);
            *(float4*)(Xs + (4 * eb + 2) * XSTRIDE + 4 * jb) = make_float4(r0.z, r1.z, r2.z, r3.z);
            *(float4*)(Xs + (4 * eb + 3) * XSTRIDE + 4 * jb) = make_float4(r0.w, r1.w, r2.w, r3.w);
        }
    }
    __syncthreads();

    // ---- per-thread top-K (sorted ascending register list of packed keys) ----
    ull best[KNB];
    #pragma unroll
    for (int n = 0; n < KNB; n++) best[n] = 0ull;
    ull  warpThr = 0ull;        // warp-wide valid discard bound
    ull  gate    = 0ull;        // max(warpThr, best[0])
    float gateF  = LOGIT_THR;   // single-compare gate (subsumes edge threshold)

    // ---- main loop: 8 passes; warp owns adjacent row block {4m..4m+3},
    //      m = 8*pass + (pass odd ? 7-w : w)  -> exactly 4080 MLP points per warp ----
    for (int pass = 0; pass < 8; pass++) {
        const int m  = 8 * pass + ((pass & 1) ? (7 - w) : w);   // 0..63
        const int rbase0 = 4 * m;

        // 4x256 gram block: 32 accumulators; ONE LDS.128 broadcast serves 4 rows
        float a00=0,a01=0,a02=0,a03=0,a04=0,a05=0,a06=0,a07=0;
        float a10=0,a11=0,a12=0,a13=0,a14=0,a15=0,a16=0,a17=0;
        float a20=0,a21=0,a22=0,a23=0,a24=0,a25=0,a26=0,a27=0;
        float a30=0,a31=0,a32=0,a33=0,a34=0,a35=0,a36=0,a37=0;

        const float* bp = Xs;
        #pragma unroll 8
        for (int e = 0; e < E; e++) {
            float4 A  = *(const float4*)(bp + 4 * l);
            float4 Bv = *(const float4*)(bp + 128 + 4 * l);
            float4 X4 = *(const float4*)(bp + rbase0);      // broadcast: rows 4m..4m+3
            float x0 = X4.x, x1 = X4.y, x2 = X4.z, x3 = X4.w;
            a00=fmaf(x0,A.x,a00); a01=fmaf(x0,A.y,a01); a02=fmaf(x0,A.z,a02); a03=fmaf(x0,A.w,a03);
            a04=fmaf(x0,Bv.x,a04);a05=fmaf(x0,Bv.y,a05);a06=fmaf(x0,Bv.z,a06);a07=fmaf(x0,Bv.w,a07);
            a10=fmaf(x1,A.x,a10); a11=fmaf(x1,A.y,a11); a12=fmaf(x1,A.z,a12); a13=fmaf(x1,A.w,a13);
            a14=fmaf(x1,Bv.x,a14);a15=fmaf(x1,Bv.y,a15);a16=fmaf(x1,Bv.z,a16);a17=fmaf(x1,Bv.w,a17);
            a20=fmaf(x2,A.x,a20); a21=fmaf(x2,A.y,a21); a22=fmaf(x2,A.z,a22); a23=fmaf(x2,A.w,a23);
            a24=fmaf(x2,Bv.x,a24);a25=fmaf(x2,Bv.y,a25);a26=fmaf(x2,Bv.z,a26);a27=fmaf(x2,Bv.w,a27);
            a30=fmaf(x3,A.x,a30); a31=fmaf(x3,A.y,a31); a32=fmaf(x3,A.z,a32); a33=fmaf(x3,A.w,a33);
            a34=fmaf(x3,Bv.x,a34);a35=fmaf(x3,Bv.y,a35);a36=fmaf(x3,Bv.z,a36);a37=fmaf(x3,Bv.w,a37);
            bp += XSTRIDE;
        }

        // row norms (over ALL 256 cols) + normalized store to srow
        #define DO_NORM(A0,A1,A2,A3,A4,A5,A6,A7,Q)                                       \
        {                                                                                \
            float nsq = A0*A0+A1*A1+A2*A2+A3*A3+A4*A4+A5*A5+A6*A6+A7*A7;                 \
            _Pragma("unroll")                                                            \
            for (int o = 16; o > 0; o >>= 1) nsq += __shfl_xor_sync(0xffffffffu,nsq,o);  \
            float inv = 1.0f / fmaxf(sqrtf(nsq), 1e-12f);                                \
            float* rb_ = srow + ((w << 2) + (Q)) * S;                                    \
            *(float4*)(rb_ + 4*l)       = make_float4(A0*inv, A1*inv, A2*inv, A3*inv);   \
            *(float4*)(rb_ + 128 + 4*l) = make_float4(A4*inv, A5*inv, A6*inv, A7*inv);   \
        }
        DO_NORM(a00,a01,a02,a03,a04,a05,a06,a07,0)
        DO_NORM(a10,a11,a12,a13,a14,a15,a16,a17,1)
        DO_NORM(a20,a21,a22,a23,a24,a25,a26,a27,2)
        DO_NORM(a30,a31,a32,a33,a34,a35,a36,a37,3)
        #undef DO_NORM
        __syncwarp();

        // refresh warp-wide threshold once per pass
        {
            ull t2 = wmax64(best[0]);
            warpThr = (t2 > warpThr) ? t2 : warpThr;
            gate = (warpThr > best[0]) ? warpThr : best[0];
            gateF = fmaxf(keyval(gate), LOGIT_THR);
        }

        // ---- MLP (logit space) + gated top-k over this warp's 4 rows ----
        float c1[16], c2[16], cw2[16];
        #pragma unroll
        for (int k = 0; k < 16; k++) {
            c1[k]  = s_wt[k];
            c2[k]  = s_wt[16 + k];
            cw2[k] = s_wt[64 + k];
        }
        const float b2v = s_wt[80];

        #pragma unroll
        for (int qq = 0; qq < 4; qq++) {
            const int i = rbase0 + qq;
            const float* rb = srow + ((w << 2) + qq) * S;
            const float twi = s_tw[i];
            const float wvi = s_iw[i];
            float rbase[16];
            #pragma unroll
            for (int k = 0; k < 16; k++)
                rbase[k] = fmaf(s_wt[32 + k], wvi, s_wt[48 + k]);   // a3*iw + b1

            const int flatbase = i << 8;
            for (int j = i + 1 + l; j < S; j += 32) {
                float s = rb[j];
                float t = twi * s_tw[j];
                float acc = b2v;
                #pragma unroll
                for (int k = 0; k < 16; k++) {
                    float pre = fmaf(c1[k], s, fmaf(c2[k], t, rbase[k]));
                    acc = fmaf(fmaxf(pre, 0.0f), cw2[k], acc);
                }
                // single float gate (covers threshold + current admission bound)
                if (acc >= gateF) {
                    ull key = ((ull)f2ord(acc) << 32)
                            | (ull)(0xffffffffu - (unsigned)(flatbase + j));
                    if (key > gate) {
                        best[0] = key;
                        #pragma unroll
                        for (int n = 0; n < KNB - 1; n++) {
                            ull x = best[n], y = best[n + 1];
                            ull lo = (x < y) ? x : y;
                            ull hi = (x < y) ? y : x;
                            best[n] = lo; best[n + 1] = hi;
                        }
                        gate = (warpThr > best[0]) ? warpThr : best[0];
                        gateF = fmaxf(keyval(gate), LOGIT_THR);
                    }
                }
            }
        }
        __syncwarp();
    }

    // ---- hierarchical merge: dump sorted lists -> warp top-20 -> CTA top-20 ----
    __syncthreads();                       // all warps done with Xs/srow
    ull* dump = (ull*)sm;                  // 256*20 ull = 40KB (inside Xs region)
    #pragma unroll
    for (int n = 0; n < KNB; n++) dump[tid * KNB + n] = best[n];
    __syncthreads();

    ull* wtop = (ull*)(sm + SROW_OFF);     // 8*20 ull
    {
        const ull* ml = dump + tid * KNB;  // own sorted-ascending list
        int p = KNB - 1;
        ull cand = ml[p];
        for (int r = 0; r < KNB; r++) {
            ull m = wmax64(cand);
            if (cand == m && m != 0ull) { p--; cand = (p >= 0) ? ml[p] : 0ull; }
            if (l == 0) wtop[w * KNB + r] = m;     // descending
        }
    }
    __syncthreads();

    if (w == 0) {
        float* oSrc = out;
        float* oDst = out + S * KNB;        // 5120
        float* oW   = out + 2 * S * KNB;    // 10240
        int p = 0;
        ull cand = (l < NWARPS) ? wtop[l * KNB] : 0ull;
        for (int r = 0; r < KNB; r++) {
            ull m = wmax64(cand);
            if (l < NWARPS && cand == m && m != 0ull) {
                p++;
                cand = (p < KNB) ? wtop[l * KNB + p] : 0ull;
            }
            if (l == 0) {
                int slot = b * KNB + r;
                if (m != 0ull) {
                    float acc = keyval(m);
                    float val = __fdividef(1.0f, 1.0f + __expf(-acc));   // sigmoid (20/batch)
                    unsigned flat = 0xffffffffu - (unsigned)(m & 0xffffffffu);
                    int ii = flat >> 8, jj = flat & 255;
                    oSrc[slot] = (float)(b * S + ii);
                    oDst[slot] = (float)(b * S + jj);
                    oW[slot]   = val;
                } else {
                    oSrc[slot] = 0.0f; oDst[slot] = 0.0f; oW[slot] = 0.0f;
                }
            }
        }
    }
}

extern "C" void kernel_launch(void* const* d_in, const int* in_sizes, int n_in,
                              void* d_out, int out_size)
{
    // metadata order: user_embeddings(unused), item_embeddings, timestamps,
    // interaction_weights, W1, b1, W2, b2, k_neighbors(=20, hardcoded)
    const float* item = (const float*)d_in[1];
    const float* tsg  = (const float*)d_in[2];
    const float* iwg  = (const float*)d_in[3];
    const float* W1   = (const float*)d_in[4];
    const float* b1   = (const float*)d_in[5];
    const float* W2   = (const float*)d_in[6];
    const float* b2   = (const float*)d_in[7];
    float* out = (float*)d_out;

    cudaFuncSetAttribute(ugc_kernel, cudaFuncAttributeMaxDynamicSharedMemorySize, SMEM_BYTES);
    ugc_kernel<<<S, NTHREADS, SMEM_BYTES>>>(item, tsg, iwg, W1, b1, W2, b2, out);
}